// round 6
// baseline (speedup 1.0000x reference)
#include <cuda_runtime.h>

// LSQ quantizer with Hadamard rotation, exploiting H = H_sylvester * diag(signs) / sqrt(D):
//   out = FWHT( signs * ( rint(clip( (FWHT(x)*inv*signs)/s, -8, 7)) * s ) ) * inv
// where inv = D^{-1/2}, signs[j] = sign(hadamard[0][j]).
// D = 2048 fixed. One CTA of 256 threads per row, 8 elements/thread.

#define D_DIM 2048
#define TPB 256

__device__ __forceinline__ void bfly(float& a, float& b) {
    float t = a;
    a = t + b;
    b = t - b;
}

// 3 butterfly stages over the register-index bits (covers 3 FWHT stages).
__device__ __forceinline__ void reg_fwht8(float r[8]) {
    bfly(r[0], r[1]); bfly(r[2], r[3]); bfly(r[4], r[5]); bfly(r[6], r[7]);
    bfly(r[0], r[2]); bfly(r[1], r[3]); bfly(r[4], r[6]); bfly(r[5], r[7]);
    bfly(r[0], r[4]); bfly(r[1], r[5]); bfly(r[2], r[6]); bfly(r[3], r[7]);
}

// 5 butterfly stages over the lane bits (element strides 8..128 in contiguous layout).
__device__ __forceinline__ void shfl_fwht(float r[8], unsigned lane) {
#pragma unroll
    for (int m = 1; m <= 16; m <<= 1) {
        bool hi = (lane & m) != 0;
#pragma unroll
        for (int k = 0; k < 8; k++) {
            float v = __shfl_xor_sync(0xffffffffu, r[k], m);
            r[k] = hi ? (v - r[k]) : (r[k] + v);
        }
    }
}

// Bank-conflict-free swizzle for the contiguous<->strided smem transpose.
__device__ __forceinline__ int sw(int a) { return a ^ ((a >> 5) & 7); }

__global__ void __launch_bounds__(TPB)
lsq_fwht_kernel(const float* __restrict__ x,
                const float* __restrict__ scale,
                const float* __restrict__ hadamard,
                float* __restrict__ out) {
    __shared__ float sm[D_DIM];

    const int row = blockIdx.x;
    const int t = threadIdx.x;
    const unsigned lane = t & 31;
    const float* xr = x + (size_t)row * D_DIM;
    float* yr = out + (size_t)row * D_DIM;

    // ---- load (contiguous, vectorized) ----
    float r[8];
    {
        float4 v0 = *reinterpret_cast<const float4*>(xr + t * 8);
        float4 v1 = *reinterpret_cast<const float4*>(xr + t * 8 + 4);
        r[0] = v0.x; r[1] = v0.y; r[2] = v0.z; r[3] = v0.w;
        r[4] = v1.x; r[5] = v1.y; r[6] = v1.z; r[7] = v1.w;
    }

    // ---- FWHT #1 ----
    reg_fwht8(r);        // strides 1,2,4   (element bits 0..2 = reg bits)
    shfl_fwht(r, lane);  // strides 8..128  (element bits 3..7 = lane bits)

    // transpose contiguous (elem = 8t+k) -> strided (elem = t + 256k)
#pragma unroll
    for (int k = 0; k < 8; k++) sm[sw(t * 8 + k)] = r[k];
    __syncthreads();
#pragma unroll
    for (int k = 0; k < 8; k++) r[k] = sm[sw(t + 256 * k)];

    reg_fwht8(r);        // strides 256,512,1024 (now reg bits) — FWHT #1 done

    // ---- quantize (LSQ forward: s = scale[0]) ----
    const float inv = 0.02209708691207961f;  // 2048^-0.5
    const float s = scale[0];
#pragma unroll
    for (int k = 0; k < 8; k++) {
        int j = t + 256 * k;
        float sg = (hadamard[j] < 0.0f) ? -1.0f : 1.0f;  // sign of H[0][j]
        float v = r[k] * inv * sg;                        // x_rot element
        float xq = fminf(fmaxf(v / s, -8.0f), 7.0f);      // clip(x_rot/s, -Qn, Qp)
        float y = rintf(xq) * s;                          // round-half-even * s
        r[k] = y * sg;                                    // pre-apply signs for FWHT #2
    }

    // ---- FWHT #2 (stages commute: do reg-bit stages first in current layout) ----
    reg_fwht8(r);        // strides 256,512,1024

    __syncthreads();     // all reads of first transpose complete before reuse
#pragma unroll
    for (int k = 0; k < 8; k++) sm[sw(t + 256 * k)] = r[k];
    __syncthreads();
#pragma unroll
    for (int k = 0; k < 8; k++) r[k] = sm[sw(t * 8 + k)];

    shfl_fwht(r, lane);  // strides 8..128
    reg_fwht8(r);        // strides 1,2,4 — FWHT #2 done

    // ---- store (contiguous, vectorized), apply final 1/sqrt(D) ----
    {
        float4 o0 = make_float4(r[0] * inv, r[1] * inv, r[2] * inv, r[3] * inv);
        float4 o1 = make_float4(r[4] * inv, r[5] * inv, r[6] * inv, r[7] * inv);
        *reinterpret_cast<float4*>(yr + t * 8) = o0;
        *reinterpret_cast<float4*>(yr + t * 8 + 4) = o1;
    }
}

extern "C" void kernel_launch(void* const* d_in, const int* in_sizes, int n_in,
                              void* d_out, int out_size) {
    const float* x = (const float*)d_in[0];
    const float* scale = (const float*)d_in[1];
    const float* hadamard = (const float*)d_in[2];
    float* out = (float*)d_out;

    int rows = in_sizes[0] / D_DIM;  // B*S = 16384
    lsq_fwht_kernel<<<rows, TPB>>>(x, scale, hadamard, out);
}

// round 7
// speedup vs baseline: 1.0173x; 1.0173x over previous
#include <cuda_runtime.h>

// LSQ quantizer with Hadamard rotation, exploiting H = H_sylvester * diag(signs) / sqrt(D):
//   out = FWHT( signs * ( rint(clip( (FWHT(x)*inv*signs)/s, -8, 7)) * s ) ) * inv
// where inv = D^{-1/2}, signs[j] = sign(hadamard[0][j]).
// D = 2048 fixed. One CTA of 256 threads per row, 8 elements/thread.

#define D_DIM 2048
#define TPB 256

__device__ __forceinline__ void bfly(float& a, float& b) {
    float t = a;
    a = t + b;
    b = t - b;
}

// 3 butterfly stages over the register-index bits (covers 3 FWHT stages).
__device__ __forceinline__ void reg_fwht8(float r[8]) {
    bfly(r[0], r[1]); bfly(r[2], r[3]); bfly(r[4], r[5]); bfly(r[6], r[7]);
    bfly(r[0], r[2]); bfly(r[1], r[3]); bfly(r[4], r[6]); bfly(r[5], r[7]);
    bfly(r[0], r[4]); bfly(r[1], r[5]); bfly(r[2], r[6]); bfly(r[3], r[7]);
}

// 5 butterfly stages over the lane bits (element strides 8..128 in contiguous layout).
__device__ __forceinline__ void shfl_fwht(float r[8], unsigned lane) {
#pragma unroll
    for (int m = 1; m <= 16; m <<= 1) {
        bool hi = (lane & m) != 0;
#pragma unroll
        for (int k = 0; k < 8; k++) {
            float v = __shfl_xor_sync(0xffffffffu, r[k], m);
            r[k] = hi ? (v - r[k]) : (r[k] + v);
        }
    }
}

// Bank-conflict-free swizzle for the contiguous<->strided smem transpose.
__device__ __forceinline__ int sw(int a) { return a ^ ((a >> 5) & 7); }

__global__ void __launch_bounds__(TPB)
lsq_fwht_kernel(const float* __restrict__ x,
                const float* __restrict__ scale,
                const float* __restrict__ hadamard,
                float* __restrict__ out) {
    __shared__ float sm[D_DIM];

    const int row = blockIdx.x;
    const int t = threadIdx.x;
    const unsigned lane = t & 31;
    const float* xr = x + (size_t)row * D_DIM;
    float* yr = out + (size_t)row * D_DIM;

    // ---- load (contiguous, vectorized) ----
    float r[8];
    {
        float4 v0 = *reinterpret_cast<const float4*>(xr + t * 8);
        float4 v1 = *reinterpret_cast<const float4*>(xr + t * 8 + 4);
        r[0] = v0.x; r[1] = v0.y; r[2] = v0.z; r[3] = v0.w;
        r[4] = v1.x; r[5] = v1.y; r[6] = v1.z; r[7] = v1.w;
    }

    // ---- FWHT #1 ----
    reg_fwht8(r);        // strides 1,2,4   (element bits 0..2 = reg bits)
    shfl_fwht(r, lane);  // strides 8..128  (element bits 3..7 = lane bits)

    // transpose contiguous (elem = 8t+k) -> strided (elem = t + 256k)
#pragma unroll
    for (int k = 0; k < 8; k++) sm[sw(t * 8 + k)] = r[k];
    __syncthreads();
#pragma unroll
    for (int k = 0; k < 8; k++) r[k] = sm[sw(t + 256 * k)];

    reg_fwht8(r);        // strides 256,512,1024 (now reg bits) — FWHT #1 done

    // ---- quantize (LSQ forward: s = scale[0]) ----
    const float inv = 0.02209708691207961f;  // 2048^-0.5
    const float s = scale[0];
#pragma unroll
    for (int k = 0; k < 8; k++) {
        int j = t + 256 * k;
        float sg = (hadamard[j] < 0.0f) ? -1.0f : 1.0f;  // sign of H[0][j]
        float v = r[k] * inv * sg;                        // x_rot element
        float xq = fminf(fmaxf(v / s, -8.0f), 7.0f);      // clip(x_rot/s, -Qn, Qp)
        float y = rintf(xq) * s;                          // round-half-even * s
        r[k] = y * sg;                                    // pre-apply signs for FWHT #2
    }

    // ---- FWHT #2 (stages commute: do reg-bit stages first in current layout) ----
    reg_fwht8(r);        // strides 256,512,1024

    __syncthreads();     // all reads of first transpose complete before reuse
#pragma unroll
    for (int k = 0; k < 8; k++) sm[sw(t + 256 * k)] = r[k];
    __syncthreads();
#pragma unroll
    for (int k = 0; k < 8; k++) r[k] = sm[sw(t * 8 + k)];

    shfl_fwht(r, lane);  // strides 8..128
    reg_fwht8(r);        // strides 1,2,4 — FWHT #2 done

    // ---- store (contiguous, vectorized), apply final 1/sqrt(D) ----
    {
        float4 o0 = make_float4(r[0] * inv, r[1] * inv, r[2] * inv, r[3] * inv);
        float4 o1 = make_float4(r[4] * inv, r[5] * inv, r[6] * inv, r[7] * inv);
        *reinterpret_cast<float4*>(yr + t * 8) = o0;
        *reinterpret_cast<float4*>(yr + t * 8 + 4) = o1;
    }
}

extern "C" void kernel_launch(void* const* d_in, const int* in_sizes, int n_in,
                              void* d_out, int out_size) {
    const float* x = (const float*)d_in[0];
    const float* scale = (const float*)d_in[1];
    const float* hadamard = (const float*)d_in[2];
    float* out = (float*)d_out;

    int rows = in_sizes[0] / D_DIM;  // B*S = 16384
    lsq_fwht_kernel<<<rows, TPB>>>(x, scale, hadamard, out);
}